// round 11
// baseline (speedup 1.0000x reference)
#include <cuda_runtime.h>

// CfC / liquid-net recurrent cell. One thread per pixel, everything register
// resident (zk NEVER goes through shared memory), packed f32x2 math, weights
// read from smem with warp-uniform (broadcast) addresses only.
// Shapes: B=4, C=16, T=32, H=64, W=64 -> 16384 pixels; UNITS=32, BACKBONE=64.
// ts == 1.0 so Wt = Wta+Wtb, bt = bta+btb.
// Constant folding: backbone weights/bias pre-scaled by 0.666 (lecun inner),
// head weights pre-scaled by 1.7159 (lecun outer) -> z = tanh(acc) plain.

#define CC   16
#define TT   32
#define UU   32
#define BKB  64
#define HWSZ 4096
#define NTHREADS 128
#define NBLOCKS  128            // 128*128 = 16384 pixels exactly

typedef unsigned long long u64;

__device__ __forceinline__ void ffma2(u64& d, u64 a, u64 b) {
    asm("fma.rn.f32x2 %0, %1, %2, %0;" : "+l"(d) : "l"(a), "l"(b));
}
__device__ __forceinline__ u64 fadd2(u64 a, u64 b) {
    u64 d; asm("add.rn.f32x2 %0, %1, %2;" : "=l"(d) : "l"(a), "l"(b)); return d;
}
__device__ __forceinline__ u64 pack2(float lo, float hi) {
    u64 d; asm("mov.b64 %0, {%1, %2};" : "=l"(d) : "f"(lo), "f"(hi)); return d;
}
__device__ __forceinline__ void unpack2(u64 v, float& lo, float& hi) {
    asm("mov.b64 {%0, %1}, %2;" : "=f"(lo), "=f"(hi) : "l"(v));
}
__device__ __forceinline__ float fast_tanh(float x) {
    float e = __expf(-2.0f * x);
    return __fdividef(2.0f, e + 1.0f) - 1.0f;
}
__device__ __forceinline__ float fast_sig(float x) {
    return __fdividef(1.0f, 1.0f + __expf(-x));
}

// Shared memory (floats / u64), all 16B-aligned, broadcast-read only:
//   Wbx [64][16]  (x 0.666)        floats [0, 1024)
//   Wbh [64][32]  (x 0.666)        floats [1024, 3072)
//   W1t [64][32]  c-major, x1.7159 floats [3072, 5120)
//   W2t [64][32]                   floats [5120, 7168)
//   Wtt [64][32]  (Wta+Wtb)x1.7159 floats [7168, 9216)
//   bb  [64]      (x 0.666)        floats [9216, 9280)
//   b1q/b2q/btq [16] u64 bias pairs  at float offset 9280 (= u64 idx 4640)
#define OFF_WBX 0
#define OFF_WBH 1024
#define OFF_W1  3072
#define OFF_W2  5120
#define OFF_WT  7168
#define OFF_BB  9216
#define OFF_BQ  9280                 // u64 region: 3*16 u64 = 48 u64 = 384 B
#define SMEM_FLOATS (OFF_BQ + 96)
#define SMEM_BYTES  (SMEM_FLOATS * 4)

__global__ void __launch_bounds__(NTHREADS, 1)
cfc_scan_kernel(const float* __restrict__ x,
                const float* __restrict__ Wb,  const float* __restrict__ bb,
                const float* __restrict__ W1,  const float* __restrict__ b1,
                const float* __restrict__ W2,  const float* __restrict__ b2,
                const float* __restrict__ Wta, const float* __restrict__ bta,
                const float* __restrict__ Wtb, const float* __restrict__ btb,
                float* __restrict__ out)
{
    extern __shared__ float s_f[];
    u64* s_bq = (u64*)(s_f + OFF_BQ);   // [0..15]=b1 pairs, [16..31]=b2, [32..47]=bt

    const int tid = threadIdx.x;

    // ---- stage weights (with constant folding) ----
    for (int i = tid; i < BKB * 48; i += NTHREADS) {
        int k = i / 48, c = i % 48;
        float v = Wb[i] * 0.666f;
        if (c < 16) s_f[OFF_WBX + k * 16 + c] = v;
        else        s_f[OFF_WBH + k * 32 + (c - 16)] = v;
    }
    for (int i = tid; i < UU * BKB; i += NTHREADS) {
        int u = i / BKB, c = i % BKB;            // row-major [u][c] -> c-major [c][u]
        s_f[OFF_W1 + c * UU + u] = W1[i] * 1.7159f;
        s_f[OFF_W2 + c * UU + u] = W2[i] * 1.7159f;
        s_f[OFF_WT + c * UU + u] = (Wta[i] + Wtb[i]) * 1.7159f;
    }
    if (tid < BKB) s_f[OFF_BB + tid] = bb[tid] * 0.666f;
    if (tid < 16) {
        s_bq[tid]      = pack2(b1[2 * tid], b1[2 * tid + 1]);
        s_bq[16 + tid] = pack2(b2[2 * tid], b2[2 * tid + 1]);
        s_bq[32 + tid] = pack2(bta[2 * tid] + btb[2 * tid],
                               bta[2 * tid + 1] + btb[2 * tid + 1]);
    }
    __syncthreads();

    // ---- per-thread pixel ----
    const int p  = blockIdx.x * NTHREADS + tid;  // 0..16383
    const int b  = p >> 12;
    const int hw = p & 4095;
    const float* xb = x   + ((size_t)b * CC) * (TT * HWSZ) + hw;   // x[b,c,t,hw]
    float*       ob = out + ((size_t)b * UU) * (TT * HWSZ) + hw;   // out[b,u,t,hw]

    u64 hp[UU / 2];                              // packed h pairs
#pragma unroll
    for (int m = 0; m < UU / 2; m++) hp[m] = 0ull;

    // x for step 0
    float xv[CC];
#pragma unroll
    for (int c = 0; c < CC; c++) xv[c] = xb[c * (TT * HWSZ)];

    for (int t = 0; t < TT; t++) {
        u64 xp[CC / 2];
#pragma unroll
        for (int m = 0; m < CC / 2; m++) xp[m] = pack2(xv[2 * m], xv[2 * m + 1]);

        // prefetch next step's x (slack ~9k cycles); t=31 reloads t=31 (harmless)
        const int tn = (t < TT - 1) ? t + 1 : t;
#pragma unroll
        for (int c = 0; c < CC; c++) xv[c] = xb[(c * TT + tn) * HWSZ];

        // ---- backbone: zf[k] = tanh(0.666*(W@[x;h]+b)), folded ----
        float zf[BKB];
#pragma unroll
        for (int k = 0; k < BKB; k++) {
            const ulonglong2* wx = (const ulonglong2*)(s_f + OFF_WBX + k * 16);
            const ulonglong2* wh = (const ulonglong2*)(s_f + OFF_WBH + k * 32);
            u64 a0 = 0ull, a1 = 0ull, a2 = 0ull, a3 = 0ull;
#pragma unroll
            for (int m = 0; m < 4; m++) {
                ulonglong2 w = wx[m];
                ffma2(a0, w.x, xp[2 * m]);
                ffma2(a1, w.y, xp[2 * m + 1]);
            }
#pragma unroll
            for (int m = 0; m < 4; m++) {
                ulonglong2 w0 = wh[2 * m];
                ulonglong2 w1 = wh[2 * m + 1];
                ffma2(a2, w0.x, hp[4 * m]);
                ffma2(a3, w0.y, hp[4 * m + 1]);
                ffma2(a0, w1.x, hp[4 * m + 2]);
                ffma2(a1, w1.y, hp[4 * m + 3]);
            }
            u64 s = fadd2(fadd2(a0, a1), fadd2(a2, a3));
            float lo, hi; unpack2(s, lo, hi);
            zf[k] = fast_tanh(lo + hi + s_f[OFF_BB + k]);
        }

        // ---- heads: two groups of 16 units; zk from registers ----
#pragma unroll
        for (int g = 0; g < 2; g++) {
            const int u0 = g * 16;
            u64 A1[8], A2[8], AT[8];
#pragma unroll
            for (int m = 0; m < 8; m++) { A1[m] = 0ull; A2[m] = 0ull; AT[m] = 0ull; }
#pragma unroll
            for (int c = 0; c < BKB; c++) {
                u64 qq = pack2(zf[c], zf[c]);            // duplicated-packed z_c
                const ulonglong2* w1p = (const ulonglong2*)(s_f + OFF_W1 + c * UU + u0);
                const ulonglong2* w2p = (const ulonglong2*)(s_f + OFF_W2 + c * UU + u0);
                const ulonglong2* wtp = (const ulonglong2*)(s_f + OFF_WT + c * UU + u0);
#pragma unroll
                for (int m = 0; m < 4; m++) {
                    ulonglong2 w1 = w1p[m];
                    ffma2(A1[2 * m], w1.x, qq); ffma2(A1[2 * m + 1], w1.y, qq);
                }
#pragma unroll
                for (int m = 0; m < 4; m++) {
                    ulonglong2 w2 = w2p[m];
                    ffma2(A2[2 * m], w2.x, qq); ffma2(A2[2 * m + 1], w2.y, qq);
                }
#pragma unroll
                for (int m = 0; m < 4; m++) {
                    ulonglong2 wt = wtp[m];
                    ffma2(AT[2 * m], wt.x, qq); ffma2(AT[2 * m + 1], wt.y, qq);
                }
            }
#pragma unroll
            for (int m = 0; m < 8; m++) {
                const int u = u0 + 2 * m;
                u64 v1 = fadd2(A1[m], s_bq[g * 8 + m]);
                u64 v2 = fadd2(A2[m], s_bq[16 + g * 8 + m]);
                u64 vt = fadd2(AT[m], s_bq[32 + g * 8 + m]);
                float p0, p1, q0, q1, r0, r1;
                unpack2(v1, p0, p1);
                unpack2(v2, q0, q1);
                unpack2(vt, r0, r1);
                float f10 = fast_tanh(p0), f11 = fast_tanh(p1);
                float f20 = fast_tanh(q0), f21 = fast_tanh(q1);
                float ti0 = fast_sig(r0),  ti1 = fast_sig(r1);
                float h0 = f10 + ti0 * (f20 - f10);      // ff1*(1-ti) + ti*ff2
                float h1 = f11 + ti1 * (f21 - f11);
                hp[g * 8 + m] = pack2(h0, h1);
                ob[((u) * TT + t) * HWSZ]     = h0;      // out[b,u,t,hw]
                ob[((u + 1) * TT + t) * HWSZ] = h1;
            }
        }
    }
}

extern "C" void kernel_launch(void* const* d_in, const int* in_sizes, int n_in,
                              void* d_out, int out_size)
{
    const float* x   = (const float*)d_in[0];
    const float* Wb  = (const float*)d_in[1];
    const float* bb  = (const float*)d_in[2];
    const float* W1  = (const float*)d_in[3];
    const float* b1  = (const float*)d_in[4];
    const float* W2  = (const float*)d_in[5];
    const float* b2  = (const float*)d_in[6];
    const float* Wta = (const float*)d_in[7];
    const float* bta = (const float*)d_in[8];
    const float* Wtb = (const float*)d_in[9];
    const float* btb = (const float*)d_in[10];
    float* out = (float*)d_out;

    cudaFuncSetAttribute(cfc_scan_kernel,
                         cudaFuncAttributeMaxDynamicSharedMemorySize, SMEM_BYTES);

    cfc_scan_kernel<<<NBLOCKS, NTHREADS, SMEM_BYTES>>>(
        x, Wb, bb, W1, b1, W2, b2, Wta, bta, Wtb, btb, out);
}